// round 9
// baseline (speedup 1.0000x reference)
#include <cuda_runtime.h>
#include <cstdint>

// Problem constants
#define Bsz 16
#define Jn  16
#define Cn  64
#define HW  65536              // 256*256
#define HW4 16384              // float4s per channel
#define NCH (Bsz * Jn)         // 256 channels
#define SEG 2                  // CTAs per channel
#define NCTA (NCH * SEG)       // 512 CTAs
#define TPB 256
#define SEGF4 (HW4 / SEG)      // 8192 float4s per segment
#define BATCH 8
#define NITER (SEGF4 / (TPB * BATCH))   // 4 iterations

// Device-global scratch (allocation-free; zero-initialized at load)
__device__ unsigned long long g_pack[NCH];  // (ordf(val)<<32) | (0xFFFFFFFF - idx)
__device__ int                g_cnt[NCH];   // segments done per channel
__device__ float              g_joint[NCH]; // per-(b,j) SSE over C
__device__ int                g_done;       // channels completed

__device__ __forceinline__ unsigned ordf(float f) {
    unsigned u = __float_as_uint(f);
    return (u & 0x80000000u) ? ~u : (u | 0x80000000u);
}

// ---------------------------------------------------------------------------
__global__ __launch_bounds__(TPB, 4)
void fused_label_loss(const float* __restrict__ heatmap,
                      const float* __restrict__ pred,
                      const float* __restrict__ gt,
                      float* __restrict__ out)
{
    const int ch  = blockIdx.x >> 1;           // channel
    const int seg = blockIdx.x & (SEG - 1);    // segment within channel
    const int tid = threadIdx.x;

    const float4* __restrict__ hm =
        reinterpret_cast<const float4*>(heatmap + (size_t)ch * HW);
    const int base = seg * SEGF4;

    float bv  = -3.402823466e+38f;
    int   bfi = base + tid;                    // winning float4 index

    #pragma unroll
    for (int it = 0; it < NITER; ++it) {
        const int i0 = base + it * (TPB * BATCH) + tid;

        // 8 independent LDG.128, front-batched (64-reg budget)
        float4 v[BATCH];
        #pragma unroll
        for (int k = 0; k < BATCH; ++k)
            v[k] = hm[i0 + k * TPB];

        #pragma unroll
        for (int k = 0; k < BATCH; ++k) {
            float m01  = fmaxf(v[k].x, v[k].y);
            float m23  = fmaxf(v[k].z, v[k].w);
            float vmax = fmaxf(m01, m23);
            // ascending index + strict '>' => first occurrence in this thread
            if (vmax > bv) { bv = vmax; bfi = i0 + k * TPB; }
        }
    }

    // Recover exact element within winning float4 (re-load; L2 hit).
    // Descending checks so the LOWEST matching element wins.
    float4 wv = hm[bfi];
    int e = 3;
    if (wv.z == bv) e = 2;
    if (wv.y == bv) e = 1;
    if (wv.x == bv) e = 0;
    int bi = bfi * 4 + e;

    // ---- block reduce: larger value wins, lower index on ties ----
    __shared__ float sv[TPB];
    __shared__ int   si[TPB];
    __shared__ float s_warp[2];
    sv[tid] = bv; si[tid] = bi;
    __syncthreads();

    for (int s = TPB / 2; s > 0; s >>= 1) {
        if (tid < s) {
            float ov = sv[tid + s];
            int   oi = si[tid + s];
            if (ov > sv[tid] || (ov == sv[tid] && oi < si[tid])) {
                sv[tid] = ov; si[tid] = oi;
            }
        }
        __syncthreads();
    }

    // ---- publish segment result; elect channel completer ----
    __shared__ int s_done, s_idx;
    if (tid == 0) {
        unsigned long long pk =
            ((unsigned long long)ordf(sv[0]) << 32) |
            (unsigned long long)(0xFFFFFFFFu - (unsigned)si[0]);
        atomicMax(&g_pack[ch], pk);
        __threadfence();
        int old = atomicAdd(&g_cnt[ch], 1);
        if (old == SEG - 1) {
            __threadfence();
            unsigned long long fin = *(volatile unsigned long long*)&g_pack[ch];
            s_idx  = (int)(0xFFFFFFFFu - (unsigned)(fin & 0xFFFFFFFFull));
            s_done = 1;
            g_pack[ch] = 0;   // reset for next graph replay
            g_cnt[ch]  = 0;
        } else {
            s_done = 0;
        }
    }
    __syncthreads();

    if (!s_done) return;

    // ---- channel completer: gather pred @ argmax, squared error over C ----
    const int idx = s_idx;
    const int b   = ch >> 4;

    if (tid < Cn) {
        float p = pred[((size_t)(b * Cn + tid)) * HW + idx];
        float g = gt[(size_t)ch * Cn + tid];
        float d = p - g;
        float acc = d * d;
        #pragma unroll
        for (int off = 16; off > 0; off >>= 1)
            acc += __shfl_xor_sync(0xFFFFFFFFu, acc, off);
        if ((tid & 31) == 0) s_warp[tid >> 5] = acc;
    }
    __syncthreads();

    // ---- last channel-completer computes the per-batch means ----
    __shared__ int s_last;
    if (tid == 0) {
        g_joint[ch] = s_warp[0] + s_warp[1];
        __threadfence();
        int old = atomicAdd(&g_done, 1);
        s_last = (old == NCH - 1);
        if (s_last) g_done = 0;            // reset for next graph replay
    }
    __syncthreads();

    if (s_last && tid < Bsz) {
        __threadfence();
        float tot = 0.f;
        #pragma unroll
        for (int j = 0; j < Jn; ++j)       // fixed order -> deterministic
            tot += *(volatile float*)&g_joint[tid * Jn + j];
        out[tid] = tot * (1.0f / (float)(Jn * Cn));
    }
}

// ---------------------------------------------------------------------------
extern "C" void kernel_launch(void* const* d_in, const int* in_sizes, int n_in,
                              void* d_out, int out_size)
{
    const float* pred    = (const float*)d_in[0];  // [B,C,H,W]
    const float* gt      = (const float*)d_in[1];  // [B,J,C]
    const float* heatmap = (const float*)d_in[2];  // [B,J,H,W]
    float* out = (float*)d_out;                    // [B]

    fused_label_loss<<<NCTA, TPB>>>(heatmap, pred, gt, out);
}

// round 10
// speedup vs baseline: 1.6441x; 1.6441x over previous
#include <cuda_runtime.h>
#include <cstdint>

// Problem constants
#define Bsz 16
#define Jn  16
#define Cn  64
#define HW  65536              // 256*256
#define HW4 16384              // float4s per channel
#define NCH (Bsz * Jn)         // 256 channels = 256 CTAs
#define TPB 512                // <- only change vs the 12.8us kernel (was 256)
#define BATCH 8                // front-batched float4 loads per iteration
#define NITER (HW4 / (TPB * BATCH))   // 4 iterations

// Device-global scratch (allocation-free; zero-initialized at load)
__device__ float g_joint[NCH];   // per-(b,j) sum of squared errors over C
__device__ int   g_done;         // CTAs completed (reset by the elected CTA)

// ---------------------------------------------------------------------------
// Fused kernel: per-(b,j) argmax over heatmap + pred gather + MSE; the last
// CTA to finish computes the per-batch means and writes out[0..15].
// ---------------------------------------------------------------------------
__global__ void fused_label_loss(const float* __restrict__ heatmap,
                                 const float* __restrict__ pred,
                                 const float* __restrict__ gt,
                                 float* __restrict__ out)
{
    const int ch  = blockIdx.x;
    const int tid = threadIdx.x;

    const float4* __restrict__ hm =
        reinterpret_cast<const float4*>(heatmap + (size_t)ch * HW);

    float bv  = -3.402823466e+38f;
    int   bfi = tid;                      // winning float4 index

    #pragma unroll
    for (int it = 0; it < NITER; ++it) {
        const int i0 = it * (TPB * BATCH) + tid;

        float4 v[BATCH];
        #pragma unroll
        for (int k = 0; k < BATCH; ++k)   // 8 independent LDG.128, front-batched
            v[k] = hm[i0 + k * TPB];

        #pragma unroll
        for (int k = 0; k < BATCH; ++k) {
            float m01  = fmaxf(v[k].x, v[k].y);
            float m23  = fmaxf(v[k].z, v[k].w);
            float vmax = fmaxf(m01, m23);
            int   fi   = i0 + k * TPB;
            // ascending fi + strict '>' => first occurrence within this thread
            if (vmax > bv) { bv = vmax; bfi = fi; }
        }
    }

    // Recover exact element within winning float4 (re-load; L2 hit).
    // Check descending so the LOWEST matching element index wins.
    float4 wv = hm[bfi];
    int e = 3;
    if (wv.z == bv) e = 2;
    if (wv.y == bv) e = 1;
    if (wv.x == bv) e = 0;
    int bi = bfi * 4 + e;

    // ---- block reduce: larger value wins, lower index on ties ----
    __shared__ float sv[TPB];
    __shared__ int   si[TPB];
    __shared__ float s_warp[2];
    sv[tid] = bv; si[tid] = bi;
    __syncthreads();

    for (int s = TPB / 2; s > 0; s >>= 1) {
        if (tid < s) {
            float ov = sv[tid + s];
            int   oi = si[tid + s];
            if (ov > sv[tid] || (ov == sv[tid] && oi < si[tid])) {
                sv[tid] = ov; si[tid] = oi;
            }
        }
        __syncthreads();
    }

    // ---- fused tail: gather pred @ argmax, squared error over C ----
    const int idx = si[0];
    const int b   = ch >> 4;              // ch / Jn

    if (tid < Cn) {
        float p = pred[((size_t)(b * Cn + tid)) * HW + idx];
        float g = gt[(size_t)ch * Cn + tid];     // (b*Jn+j)*Cn == ch*Cn
        float d = p - g;
        float acc = d * d;
        #pragma unroll
        for (int off = 16; off > 0; off >>= 1)
            acc += __shfl_xor_sync(0xFFFFFFFFu, acc, off);
        if ((tid & 31) == 0) s_warp[tid >> 5] = acc;
    }
    __syncthreads();

    // ---- last-done CTA computes the per-batch means ----
    __shared__ int s_last;
    if (tid == 0) {
        g_joint[ch] = s_warp[0] + s_warp[1];
        __threadfence();                   // make g_joint[ch] globally visible
        int old = atomicAdd(&g_done, 1);
        s_last = (old == NCH - 1);
        if (s_last) g_done = 0;            // reset for next graph replay
    }
    __syncthreads();

    if (s_last && tid < Bsz) {
        __threadfence();                   // order: counter read -> g_joint reads
        float tot = 0.f;
        #pragma unroll
        for (int j = 0; j < Jn; ++j)       // fixed order -> deterministic
            tot += *(volatile float*)&g_joint[tid * Jn + j];
        out[tid] = tot * (1.0f / (float)(Jn * Cn));
    }
}

// ---------------------------------------------------------------------------
extern "C" void kernel_launch(void* const* d_in, const int* in_sizes, int n_in,
                              void* d_out, int out_size)
{
    const float* pred    = (const float*)d_in[0];  // [B,C,H,W]
    const float* gt      = (const float*)d_in[1];  // [B,J,C]
    const float* heatmap = (const float*)d_in[2];  // [B,J,H,W]
    float* out = (float*)d_out;                    // [B]

    fused_label_loss<<<NCH, TPB>>>(heatmap, pred, gt, out);
}